// round 1
// baseline (speedup 1.0000x reference)
#include <cuda_runtime.h>
#include <math.h>
#include <stdint.h>

#define NNODES 50000
#define NEDGES 500000
#define FDIM   128
#define CLS    40

// ---------------- scratch (static device globals; no allocation) ------------
__device__ float g_A   [NNODES * FDIM];   // A' = x @ W_top + b_pre
__device__ float g_B   [NNODES * FDIM];   // B  = x @ W_bot
__device__ float g_S   [NNODES * FDIM];   // segment sum of B  -> then SUM aggregator
__device__ float g_M   [NNODES * FDIM];   // segment max of B  -> then MAX aggregator
__device__ float g_MEAN[NNODES * FDIM];
__device__ float g_H   [NNODES * FDIM];   // hidden after layer 1
__device__ float g_H2  [NNODES * FDIM];   // hidden after layer 2
__device__ float g_Wf  [513 * FDIM];      // fused W' (512 rows) + fused bias (row 512)
__device__ int   g_hist[NNODES];
__device__ int   g_off [NNODES + 1];
__device__ int   g_cur [NNODES];
__device__ int   g_ssrc[NEDGES];          // src ids grouped (counting-sorted) by dst

// ---------------- graph preprocessing (per call; reused by both layers) -----
__global__ void hist_kernel(const int* __restrict__ dst) {
    int i = blockIdx.x * blockDim.x + threadIdx.x;
    if (i < NEDGES) atomicAdd(&g_hist[dst[i]], 1);
}

__global__ void scan_kernel() {  // 1 block, 1024 threads
    __shared__ int s[1024];
    const int t = threadIdx.x;
    const int chunk = (NNODES + 1023) / 1024;  // 49
    int beg = t * chunk;
    int end = beg + chunk; if (end > NNODES) end = NNODES;
    int sum = 0;
    for (int i = beg; i < end; i++) sum += g_hist[i];
    s[t] = sum;
    __syncthreads();
    for (int d = 1; d < 1024; d <<= 1) {
        int v = (t >= d) ? s[t - d] : 0;
        __syncthreads();
        s[t] += v;
        __syncthreads();
    }
    int run = (t > 0) ? s[t - 1] : 0;  // exclusive prefix
    for (int i = beg; i < end; i++) { g_off[i] = run; run += g_hist[i]; }
    if (t == 0) g_off[NNODES] = NEDGES;
}

__global__ void scatter_kernel(const int* __restrict__ src, const int* __restrict__ dst) {
    int i = blockIdx.x * blockDim.x + threadIdx.x;
    if (i >= NEDGES) return;
    int d = dst[i];
    int p = g_off[d] + atomicAdd(&g_cur[d], 1);
    g_ssrc[p] = src[i];
}

// ---------------- warp-per-node aggregation (no float atomics) --------------
__global__ void aggregate_kernel() {
    int node = (blockIdx.x * blockDim.x + threadIdx.x) >> 5;
    if (node >= NNODES) return;
    int lane = threadIdx.x & 31;
    int beg = g_off[node], end = g_off[node + 1];
    float s0 = 0.f, s1 = 0.f, s2 = 0.f, s3 = 0.f;
    float m0 = -3.4e38f, m1 = -3.4e38f, m2 = -3.4e38f, m3 = -3.4e38f;
    for (int e = beg; e < end; e++) {
        int sv = g_ssrc[e];
        const float* rowp = g_B + (size_t)sv * FDIM;
        float v0 = rowp[lane];
        float v1 = rowp[lane + 32];
        float v2 = rowp[lane + 64];
        float v3 = rowp[lane + 96];
        s0 += v0; s1 += v1; s2 += v2; s3 += v3;
        m0 = fmaxf(m0, v0); m1 = fmaxf(m1, v1);
        m2 = fmaxf(m2, v2); m3 = fmaxf(m3, v3);
    }
    size_t o = (size_t)node * FDIM + lane;
    g_S[o] = s0; g_S[o + 32] = s1; g_S[o + 64] = s2; g_S[o + 96] = s3;
    g_M[o] = m0; g_M[o + 32] = m1; g_M[o + 64] = m2; g_M[o + 96] = m3;
}

// sum = cnt*A' + SB ; mean = sum/max(cnt,1) ; max = cnt>0 ? A' + MB : 0
__global__ void finish_kernel() {
    int idx = blockIdx.x * blockDim.x + threadIdx.x;
    if (idx >= NNODES * FDIM) return;
    int n = idx >> 7;
    float c = (float)(g_off[n + 1] - g_off[n]);
    float a = g_A[idx];
    float s = fmaf(c, a, g_S[idx]);
    g_S[idx]    = s;
    g_MEAN[idx] = s / fmaxf(c, 1.f);
    g_M[idx]    = (c > 0.f) ? (a + g_M[idx]) : 0.f;
}

// ---------------- W' = [w_post; b_post] @ w_lin (+ b_lin on bias row) -------
__global__ void fuse_kernel(const float* __restrict__ wpost, const float* __restrict__ bpost,
                            const float* __restrict__ wlin,  const float* __restrict__ blin) {
    __shared__ float srow[FDIM];
    int r = blockIdx.x;    // 0..512
    int c = threadIdx.x;   // 0..127
    const float* row = (r < 512) ? (wpost + (size_t)r * FDIM) : bpost;
    srow[c] = row[c];
    __syncthreads();
    float acc = (r == 512) ? blin[c] : 0.f;
    #pragma unroll 8
    for (int k = 0; k < FDIM; k++) acc = fmaf(srow[k], wlin[k * FDIM + c], acc);
    g_Wf[r * FDIM + c] = acc;
}

// ---------------- tiled fp32 GEMM: C = A[MxK] @ W[KxN] (+bias)(+relu) -------
#define BM 128
#define BN 64
#define BK 16

__global__ __launch_bounds__(256)
void gemm_std(const float* __restrict__ A, const float* __restrict__ W,
              const float* __restrict__ bias, float* __restrict__ C,
              int M, int K, int Nout, int relu) {
    __shared__ float As[BK][BM + 4];
    __shared__ float Ws[BK][BN];
    const int tid = threadIdx.x;
    const int tx = tid & 15;   // col group
    const int ty = tid >> 4;   // row group
    const int rowBase = blockIdx.y * BM;
    const int colBase = blockIdx.x * BN;
    float acc[8][4] = {};

    for (int k0 = 0; k0 < K; k0 += BK) {
        #pragma unroll
        for (int r = 0; r < 2; r++) {
            int id = tid + 256 * r;
            int arow = id >> 2;
            int k4 = (id & 3) * 4;
            int grow = rowBase + arow;
            float4 v = make_float4(0.f, 0.f, 0.f, 0.f);
            if (grow < M) v = *(const float4*)(A + (size_t)grow * K + k0 + k4);
            As[k4 + 0][arow] = v.x; As[k4 + 1][arow] = v.y;
            As[k4 + 2][arow] = v.z; As[k4 + 3][arow] = v.w;
        }
        {
            int wk = tid >> 4;
            int wc = (tid & 15) * 4;
            int gc = colBase + wc;
            float4 v = make_float4(0.f, 0.f, 0.f, 0.f);
            if (gc < Nout) v = *(const float4*)(W + (size_t)(k0 + wk) * Nout + gc);
            *(float4*)&Ws[wk][wc] = v;
        }
        __syncthreads();
        #pragma unroll
        for (int kk = 0; kk < BK; kk++) {
            float4 a0 = *(const float4*)&As[kk][ty * 8];
            float4 a1 = *(const float4*)&As[kk][ty * 8 + 4];
            float4 bv = *(const float4*)&Ws[kk][tx * 4];
            float a[8] = {a0.x, a0.y, a0.z, a0.w, a1.x, a1.y, a1.z, a1.w};
            float b[4] = {bv.x, bv.y, bv.z, bv.w};
            #pragma unroll
            for (int i = 0; i < 8; i++)
                #pragma unroll
                for (int j = 0; j < 4; j++)
                    acc[i][j] = fmaf(a[i], b[j], acc[i][j]);
        }
        __syncthreads();
    }

    int gc = colBase + tx * 4;
    if (gc >= Nout) return;
    float4 bb = make_float4(0.f, 0.f, 0.f, 0.f);
    if (bias) bb = *(const float4*)(bias + gc);
    #pragma unroll
    for (int i = 0; i < 8; i++) {
        int grow = rowBase + ty * 8 + i;
        if (grow >= M) continue;
        float4 o;
        o.x = acc[i][0] + bb.x; o.y = acc[i][1] + bb.y;
        o.z = acc[i][2] + bb.z; o.w = acc[i][3] + bb.w;
        if (relu) {
            o.x = fmaxf(o.x, 0.f); o.y = fmaxf(o.y, 0.f);
            o.z = fmaxf(o.z, 0.f); o.w = fmaxf(o.w, 0.f);
        }
        *(float4*)(C + (size_t)grow * Nout + gc) = o;
    }
}

// cat-GEMM: feat = [X | MEAN | MAX | SUM] (K=512), C = relu(feat @ Wf + bf), Nout=128
__global__ __launch_bounds__(256)
void gemm_cat(const float* __restrict__ X, float* __restrict__ C) {
    const int K = 512, Nout = FDIM, M = NNODES;
    __shared__ float As[BK][BM + 4];
    __shared__ float Ws[BK][BN];
    const int tid = threadIdx.x;
    const int tx = tid & 15;
    const int ty = tid >> 4;
    const int rowBase = blockIdx.y * BM;
    const int colBase = blockIdx.x * BN;
    float acc[8][4] = {};

    for (int k0 = 0; k0 < K; k0 += BK) {
        #pragma unroll
        for (int r = 0; r < 2; r++) {
            int id = tid + 256 * r;
            int arow = id >> 2;
            int kk0 = k0 + (id & 3) * 4;
            int grow = rowBase + arow;
            float4 v = make_float4(0.f, 0.f, 0.f, 0.f);
            if (grow < M) {
                int seg = kk0 >> 7;
                const float* src = (seg == 0) ? X
                                 : (seg == 1) ? g_MEAN
                                 : (seg == 2) ? g_M : g_S;
                v = *(const float4*)(src + (size_t)grow * FDIM + (kk0 & 127));
            }
            int k4 = kk0 - k0;
            As[k4 + 0][arow] = v.x; As[k4 + 1][arow] = v.y;
            As[k4 + 2][arow] = v.z; As[k4 + 3][arow] = v.w;
        }
        {
            int wk = tid >> 4;
            int wc = (tid & 15) * 4;
            int gc = colBase + wc;
            float4 v = *(const float4*)(g_Wf + (size_t)(k0 + wk) * Nout + gc);
            *(float4*)&Ws[wk][wc] = v;
        }
        __syncthreads();
        #pragma unroll
        for (int kk = 0; kk < BK; kk++) {
            float4 a0 = *(const float4*)&As[kk][ty * 8];
            float4 a1 = *(const float4*)&As[kk][ty * 8 + 4];
            float4 bv = *(const float4*)&Ws[kk][tx * 4];
            float a[8] = {a0.x, a0.y, a0.z, a0.w, a1.x, a1.y, a1.z, a1.w};
            float b[4] = {bv.x, bv.y, bv.z, bv.w};
            #pragma unroll
            for (int i = 0; i < 8; i++)
                #pragma unroll
                for (int j = 0; j < 4; j++)
                    acc[i][j] = fmaf(a[i], b[j], acc[i][j]);
        }
        __syncthreads();
    }

    int gc = colBase + tx * 4;
    float4 bb = *(const float4*)(g_Wf + 512 * FDIM + gc);
    #pragma unroll
    for (int i = 0; i < 8; i++) {
        int grow = rowBase + ty * 8 + i;
        if (grow >= M) continue;
        float4 o;
        o.x = fmaxf(acc[i][0] + bb.x, 0.f);
        o.y = fmaxf(acc[i][1] + bb.y, 0.f);
        o.z = fmaxf(acc[i][2] + bb.z, 0.f);
        o.w = fmaxf(acc[i][3] + bb.w, 0.f);
        *(float4*)(C + (size_t)grow * FDIM + gc) = o;
    }
}

// ---------------- host side -------------------------------------------------
static void run_layer(const float* Hin,
                      const float* w_pre, const float* b_pre,
                      const float* w_post, const float* b_post,
                      const float* w_lin, const float* b_lin,
                      float* pA, float* pB, float* Hout) {
    dim3 g2(2, (NNODES + BM - 1) / BM);
    // A' = Hin @ W_top + b_pre ; B = Hin @ W_bot
    gemm_std<<<g2, 256>>>(Hin, w_pre, b_pre, pA, NNODES, FDIM, FDIM, 0);
    gemm_std<<<g2, 256>>>(Hin, w_pre + FDIM * FDIM, (const float*)nullptr, pB,
                          NNODES, FDIM, FDIM, 0);
    fuse_kernel<<<513, 128>>>(w_post, b_post, w_lin, b_lin);
    aggregate_kernel<<<(NNODES + 7) / 8, 256>>>();
    finish_kernel<<<(NNODES * FDIM + 255) / 256, 256>>>();
    gemm_cat<<<g2, 256>>>(Hin, Hout);
}

extern "C" void kernel_launch(void* const* d_in, const int* in_sizes, int n_in,
                              void* d_out, int out_size) {
    const float* x      = (const float*)d_in[0];
    const int*   ei     = (const int*)  d_in[1];
    const float* w1_pre = (const float*)d_in[2];
    const float* b1_pre = (const float*)d_in[3];
    const float* w1_post= (const float*)d_in[4];
    const float* b1_post= (const float*)d_in[5];
    const float* w1_lin = (const float*)d_in[6];
    const float* b1_lin = (const float*)d_in[7];
    const float* w2_pre = (const float*)d_in[8];
    const float* b2_pre = (const float*)d_in[9];
    const float* w2_post= (const float*)d_in[10];
    const float* b2_post= (const float*)d_in[11];
    const float* w2_lin = (const float*)d_in[12];
    const float* b2_lin = (const float*)d_in[13];
    const float* w_out  = (const float*)d_in[14];
    const float* b_out  = (const float*)d_in[15];
    float* out = (float*)d_out;

    void *pA, *pB, *pH, *pH2, *pHist, *pCur;
    cudaGetSymbolAddress(&pA, g_A);
    cudaGetSymbolAddress(&pB, g_B);
    cudaGetSymbolAddress(&pH, g_H);
    cudaGetSymbolAddress(&pH2, g_H2);
    cudaGetSymbolAddress(&pHist, g_hist);
    cudaGetSymbolAddress(&pCur, g_cur);

    const int* srcp = ei;           // edge_index[0]
    const int* dstp = ei + NEDGES;  // edge_index[1]

    // counting sort of edges by dst (shared by both layers)
    cudaMemsetAsync(pHist, 0, NNODES * sizeof(int));
    cudaMemsetAsync(pCur,  0, NNODES * sizeof(int));
    hist_kernel<<<(NEDGES + 255) / 256, 256>>>(dstp);
    scan_kernel<<<1, 1024>>>();
    scatter_kernel<<<(NEDGES + 255) / 256, 256>>>(srcp, dstp);

    // layer 1: x -> g_H
    run_layer(x, w1_pre, b1_pre, w1_post, b1_post, w1_lin, b1_lin,
              (float*)pA, (float*)pB, (float*)pH);
    // layer 2: g_H -> g_H2
    run_layer((const float*)pH, w2_pre, b2_pre, w2_post, b2_post, w2_lin, b2_lin,
              (float*)pA, (float*)pB, (float*)pH2);
    // output: g_H2 @ w_out + b_out
    gemm_std<<<dim3(1, (NNODES + BM - 1) / BM), 256>>>(
        (const float*)pH2, w_out, b_out, out, NNODES, FDIM, CLS, 0);
}

// round 2
// speedup vs baseline: 2.0867x; 2.0867x over previous
#include <cuda_runtime.h>
#include <math.h>
#include <stdint.h>

#define NNODES 50000
#define NEDGES 500000
#define FDIM   128
#define CLS    40

// ---------------- scratch (static device globals; no allocation) ------------
__device__ float g_A   [NNODES * FDIM];   // A' = x @ W_top + b_pre (fp32)
__device__ float g_B   [NNODES * FDIM];   // B  = x @ W_bot        (fp32)
__device__ float g_S   [NNODES * FDIM];   // SUM aggregator  (tf32-rounded)
__device__ float g_M   [NNODES * FDIM];   // MAX aggregator  (tf32-rounded)
__device__ float g_MEAN[NNODES * FDIM];   // MEAN aggregator (tf32-rounded)
__device__ float g_H   [NNODES * FDIM];   // hidden after layer 1 (tf32-rounded)
__device__ float g_H2  [NNODES * FDIM];   // hidden after layer 2 (fp32)
__device__ float g_X   [NNODES * FDIM];   // tf32-rounded copy of x
__device__ float g_Wf  [513 * FDIM];      // fused W' (512 rows, tf32) + fused bias (fp32)
__device__ float g_WpreR[2 * 256 * FDIM]; // tf32-rounded w1_pre, w2_pre
__device__ int   g_hist[NNODES];
__device__ int   g_off [NNODES + 1];
__device__ int   g_cur [NNODES];
__device__ int   g_ssrc[NEDGES];          // src ids grouped (counting-sorted) by dst

// ---------------- helpers ---------------------------------------------------
__device__ __forceinline__ float tf32r(float x) {
    unsigned u;
    asm("cvt.rna.tf32.f32 %0, %1;" : "=r"(u) : "f"(x));
    return __uint_as_float(u);
}

__device__ __forceinline__ void cpasync16(void* dst, const void* src, bool pred) {
    unsigned sa = (unsigned)__cvta_generic_to_shared(dst);
    int sz = pred ? 16 : 0;
    asm volatile("cp.async.cg.shared.global [%0], [%1], 16, %2;\n"
                 :: "r"(sa), "l"(src), "r"(sz));
}

__device__ __forceinline__ void mma_tf32(float* c, const unsigned* a,
                                         unsigned b0, unsigned b1) {
    asm volatile(
        "mma.sync.aligned.m16n8k8.row.col.f32.tf32.tf32.f32 "
        "{%0,%1,%2,%3}, {%4,%5,%6,%7}, {%8,%9}, {%0,%1,%2,%3};"
        : "+f"(c[0]), "+f"(c[1]), "+f"(c[2]), "+f"(c[3])
        : "r"(a[0]), "r"(a[1]), "r"(a[2]), "r"(a[3]), "r"(b0), "r"(b1));
}

// ---------------- graph preprocessing ---------------------------------------
__global__ void hist_kernel(const int* __restrict__ dst) {
    int i = blockIdx.x * blockDim.x + threadIdx.x;
    if (i < NEDGES) atomicAdd(&g_hist[dst[i]], 1);
}

__global__ void scan_kernel() {  // 1 block, 1024 threads
    __shared__ int s[1024];
    const int t = threadIdx.x;
    const int chunk = (NNODES + 1023) / 1024;
    int beg = t * chunk;
    int end = beg + chunk; if (end > NNODES) end = NNODES;
    int sum = 0;
    for (int i = beg; i < end; i++) sum += g_hist[i];
    s[t] = sum;
    __syncthreads();
    for (int d = 1; d < 1024; d <<= 1) {
        int v = (t >= d) ? s[t - d] : 0;
        __syncthreads();
        s[t] += v;
        __syncthreads();
    }
    int run = (t > 0) ? s[t - 1] : 0;
    for (int i = beg; i < end; i++) { g_off[i] = run; run += g_hist[i]; }
    if (t == 0) g_off[NNODES] = NEDGES;
}

__global__ void scatter_kernel(const int* __restrict__ src, const int* __restrict__ dst) {
    int i = blockIdx.x * blockDim.x + threadIdx.x;
    if (i >= NEDGES) return;
    int d = dst[i];
    int p = g_off[d] + atomicAdd(&g_cur[d], 1);
    g_ssrc[p] = src[i];
}

// tf32-round an array (producers for the tensor-core GEMMs)
__global__ void cvt_kernel(const float* __restrict__ in, float* __restrict__ out, int n) {
    int i = blockIdx.x * blockDim.x + threadIdx.x;
    if (i < n) out[i] = tf32r(in[i]);
}

// ---------------- aggregation (warp/node) + finish, fused --------------------
// sum = cnt*A' + SB ; mean = sum/max(cnt,1) ; max = cnt>0 ? A' + MB : 0
__global__ void aggregate_kernel() {
    int node = (blockIdx.x * blockDim.x + threadIdx.x) >> 5;
    if (node >= NNODES) return;
    int lane = threadIdx.x & 31;
    int beg = g_off[node], end = g_off[node + 1];
    float s0 = 0.f, s1 = 0.f, s2 = 0.f, s3 = 0.f;
    float m0 = -3.4e38f, m1 = -3.4e38f, m2 = -3.4e38f, m3 = -3.4e38f;
    for (int e = beg; e < end; e++) {
        int sv = g_ssrc[e];
        const float* rowp = g_B + (size_t)sv * FDIM;
        float v0 = rowp[lane];
        float v1 = rowp[lane + 32];
        float v2 = rowp[lane + 64];
        float v3 = rowp[lane + 96];
        s0 += v0; s1 += v1; s2 += v2; s3 += v3;
        m0 = fmaxf(m0, v0); m1 = fmaxf(m1, v1);
        m2 = fmaxf(m2, v2); m3 = fmaxf(m3, v3);
    }
    size_t o = (size_t)node * FDIM + lane;
    float c = (float)(end - beg);
    float ic = 1.f / fmaxf(c, 1.f);
    float a0 = g_A[o], a1 = g_A[o + 32], a2 = g_A[o + 64], a3 = g_A[o + 96];
    float t0 = fmaf(c, a0, s0), t1 = fmaf(c, a1, s1);
    float t2 = fmaf(c, a2, s2), t3 = fmaf(c, a3, s3);
    g_S[o]      = tf32r(t0); g_S[o + 32]    = tf32r(t1);
    g_S[o + 64] = tf32r(t2); g_S[o + 96]    = tf32r(t3);
    g_MEAN[o]      = tf32r(t0 * ic); g_MEAN[o + 32] = tf32r(t1 * ic);
    g_MEAN[o + 64] = tf32r(t2 * ic); g_MEAN[o + 96] = tf32r(t3 * ic);
    bool nz = (c > 0.f);
    g_M[o]      = nz ? tf32r(a0 + m0) : 0.f;
    g_M[o + 32] = nz ? tf32r(a1 + m1) : 0.f;
    g_M[o + 64] = nz ? tf32r(a2 + m2) : 0.f;
    g_M[o + 96] = nz ? tf32r(a3 + m3) : 0.f;
}

// ---------------- W' = [w_post; b_post] @ w_lin (+ b_lin on bias row) -------
__global__ void fuse_kernel(const float* __restrict__ wpost, const float* __restrict__ bpost,
                            const float* __restrict__ wlin,  const float* __restrict__ blin) {
    __shared__ float srow[FDIM];
    int r = blockIdx.x;    // 0..512
    int c = threadIdx.x;   // 0..127
    const float* row = (r < 512) ? (wpost + (size_t)r * FDIM) : bpost;
    srow[c] = row[c];
    __syncthreads();
    float acc = (r == 512) ? blin[c] : 0.f;
    #pragma unroll 8
    for (int k = 0; k < FDIM; k++) acc = fmaf(srow[k], wlin[k * FDIM + c], acc);
    g_Wf[r * FDIM + c] = (r < 512) ? tf32r(acc) : acc;  // bias row stays fp32
}

// ---------------- TF32 tensor-core GEMM -------------------------------------
// Block tile 128(M) x 128(N), K-slab 32, 2-stage cp.async pipeline.
// 8 warps laid out 4(M) x 2(N); warp tile 32x64; mma m16n8k8.
// A rows come from up to 4 segment sources (row stride 128 each).
// If gridDim.x == 2: pre-GEMM mode — blockIdx.x selects weight half & output.
#define ASTRIDE 36
#define BSTRIDE 136
#define STAGEF  (128 * ASTRIDE + 32 * BSTRIDE)   // floats per stage = 8960
#define SMEM_BYTES (2 * STAGEF * 4)              // 71680

struct GemmSrcs { const float* s[4]; };

__global__ __launch_bounds__(256, 2)
void mma_gemm(GemmSrcs srcs, const float* __restrict__ W,
              const float* __restrict__ bias0,
              float* outA, float* outB,
              int M, int nIter, int relu, int round) {
    extern __shared__ float smem[];
    const int tid = threadIdx.x;
    const int bm = blockIdx.y * 128;

    const float* Wb = W;
    float* out = outA;
    const float* bias = bias0;
    if (gridDim.x == 2 && blockIdx.x == 1) {
        Wb = W + 128 * 128;
        out = outB;
        bias = nullptr;
    }

    const int lane = tid & 31, wid = tid >> 5;
    const int wm = (wid >> 1) * 32, wn = (wid & 1) * 64;
    const int fr = lane >> 2, fc = lane & 3;

    float acc[2][8][4];
    #pragma unroll
    for (int mt = 0; mt < 2; mt++)
        #pragma unroll
        for (int nt = 0; nt < 8; nt++)
            #pragma unroll
            for (int j = 0; j < 4; j++) acc[mt][nt][j] = 0.f;

    // ---- stage loader ----
    auto loadStage = [&](int it, int stage) {
        int k0 = it * 32;
        const float* sp = srcs.s[(k0 >> 7) & 3];
        int kloc = k0 & 127;
        float* As = smem + stage * STAGEF;
        float* Bs = As + 128 * ASTRIDE;
        #pragma unroll
        for (int i = 0; i < 4; i++) {
            int id = tid + 256 * i;
            int arow = id >> 3, c4 = id & 7;
            bool p = (bm + arow) < M;
            cpasync16(As + arow * ASTRIDE + c4 * 4,
                      sp + (size_t)(bm + arow) * 128 + kloc + c4 * 4, p);
        }
        #pragma unroll
        for (int i = 0; i < 4; i++) {
            int id = tid + 256 * i;
            int krow = id >> 5, c4 = id & 31;
            cpasync16(Bs + krow * BSTRIDE + c4 * 4,
                      Wb + (size_t)(k0 + krow) * 128 + c4 * 4, true);
        }
        asm volatile("cp.async.commit_group;" ::: "memory");
    };

    loadStage(0, 0);
    for (int it = 0; it < nIter; ++it) {
        int cur = it & 1;
        if (it + 1 < nIter) {
            loadStage(it + 1, cur ^ 1);
            asm volatile("cp.async.wait_group 1;" ::: "memory");
        } else {
            asm volatile("cp.async.wait_group 0;" ::: "memory");
        }
        __syncthreads();

        const float* As = smem + cur * STAGEF;
        const float* Bs = As + 128 * ASTRIDE;
        #pragma unroll
        for (int kk = 0; kk < 32; kk += 8) {
            unsigned af[2][4];
            #pragma unroll
            for (int mt = 0; mt < 2; mt++) {
                int m0 = wm + mt * 16;
                af[mt][0] = __float_as_uint(As[(m0 + fr)     * ASTRIDE + kk + fc]);
                af[mt][1] = __float_as_uint(As[(m0 + fr + 8) * ASTRIDE + kk + fc]);
                af[mt][2] = __float_as_uint(As[(m0 + fr)     * ASTRIDE + kk + fc + 4]);
                af[mt][3] = __float_as_uint(As[(m0 + fr + 8) * ASTRIDE + kk + fc + 4]);
            }
            #pragma unroll
            for (int nt = 0; nt < 8; nt++) {
                int n0 = wn + nt * 8;
                unsigned b0 = __float_as_uint(Bs[(kk + fc)     * BSTRIDE + n0 + fr]);
                unsigned b1 = __float_as_uint(Bs[(kk + 4 + fc) * BSTRIDE + n0 + fr]);
                mma_tf32(acc[0][nt], af[0], b0, b1);
                mma_tf32(acc[1][nt], af[1], b0, b1);
            }
        }
        __syncthreads();
    }

    // ---- epilogue ----
    #pragma unroll
    for (int mt = 0; mt < 2; mt++) {
        #pragma unroll
        for (int nt = 0; nt < 8; nt++) {
            int r0 = bm + wm + mt * 16 + fr;
            int cc = wn + nt * 8 + 2 * fc;
            float b0 = 0.f, b1 = 0.f;
            if (bias) { b0 = bias[cc]; b1 = bias[cc + 1]; }
            float v0 = acc[mt][nt][0] + b0, v1 = acc[mt][nt][1] + b1;
            float v2 = acc[mt][nt][2] + b0, v3 = acc[mt][nt][3] + b1;
            if (relu) {
                v0 = fmaxf(v0, 0.f); v1 = fmaxf(v1, 0.f);
                v2 = fmaxf(v2, 0.f); v3 = fmaxf(v3, 0.f);
            }
            if (round) {
                v0 = tf32r(v0); v1 = tf32r(v1);
                v2 = tf32r(v2); v3 = tf32r(v3);
            }
            if (r0 < M) {
                float2 o = make_float2(v0, v1);
                *(float2*)(out + (size_t)r0 * 128 + cc) = o;
            }
            if (r0 + 8 < M) {
                float2 o = make_float2(v2, v3);
                *(float2*)(out + (size_t)(r0 + 8) * 128 + cc) = o;
            }
        }
    }
}

// ---------------- fp32 SIMT GEMM for the small output projection ------------
#define BM 128
#define BN 64
#define BK 16

__global__ __launch_bounds__(256)
void gemm_std(const float* __restrict__ A, const float* __restrict__ W,
              const float* __restrict__ bias, float* __restrict__ C,
              int M, int K, int Nout, int relu) {
    __shared__ float As[BK][BM + 4];
    __shared__ float Ws[BK][BN];
    const int tid = threadIdx.x;
    const int tx = tid & 15;
    const int ty = tid >> 4;
    const int rowBase = blockIdx.y * BM;
    const int colBase = blockIdx.x * BN;
    float acc[8][4] = {};

    for (int k0 = 0; k0 < K; k0 += BK) {
        #pragma unroll
        for (int r = 0; r < 2; r++) {
            int id = tid + 256 * r;
            int arow = id >> 2;
            int k4 = (id & 3) * 4;
            int grow = rowBase + arow;
            float4 v = make_float4(0.f, 0.f, 0.f, 0.f);
            if (grow < M) v = *(const float4*)(A + (size_t)grow * K + k0 + k4);
            As[k4 + 0][arow] = v.x; As[k4 + 1][arow] = v.y;
            As[k4 + 2][arow] = v.z; As[k4 + 3][arow] = v.w;
        }
        {
            int wk = tid >> 4;
            int wc = (tid & 15) * 4;
            int gc = colBase + wc;
            float4 v = make_float4(0.f, 0.f, 0.f, 0.f);
            if (gc < Nout) v = *(const float4*)(W + (size_t)(k0 + wk) * Nout + gc);
            *(float4*)&Ws[wk][wc] = v;
        }
        __syncthreads();
        #pragma unroll
        for (int kk = 0; kk < BK; kk++) {
            float4 a0 = *(const float4*)&As[kk][ty * 8];
            float4 a1 = *(const float4*)&As[kk][ty * 8 + 4];
            float4 bv = *(const float4*)&Ws[kk][tx * 4];
            float a[8] = {a0.x, a0.y, a0.z, a0.w, a1.x, a1.y, a1.z, a1.w};
            float b[4] = {bv.x, bv.y, bv.z, bv.w};
            #pragma unroll
            for (int i = 0; i < 8; i++)
                #pragma unroll
                for (int j = 0; j < 4; j++)
                    acc[i][j] = fmaf(a[i], b[j], acc[i][j]);
        }
        __syncthreads();
    }

    int gc = colBase + tx * 4;
    if (gc >= Nout) return;
    float4 bb = make_float4(0.f, 0.f, 0.f, 0.f);
    if (bias) bb = *(const float4*)(bias + gc);
    #pragma unroll
    for (int i = 0; i < 8; i++) {
        int grow = rowBase + ty * 8 + i;
        if (grow >= M) continue;
        float4 o;
        o.x = acc[i][0] + bb.x; o.y = acc[i][1] + bb.y;
        o.z = acc[i][2] + bb.z; o.w = acc[i][3] + bb.w;
        if (relu) {
            o.x = fmaxf(o.x, 0.f); o.y = fmaxf(o.y, 0.f);
            o.z = fmaxf(o.z, 0.f); o.w = fmaxf(o.w, 0.f);
        }
        *(float4*)(C + (size_t)grow * Nout + gc) = o;
    }
}

// ---------------- host side -------------------------------------------------
static void run_layer(const float* HinR,          // tf32-rounded activations
                      const float* wpreR,         // tf32-rounded w_pre [256x128]
                      const float* b_pre,
                      const float* w_post, const float* b_post,
                      const float* w_lin, const float* b_lin,
                      float* pA, float* pB, float* pH,
                      float* pS, float* pM, float* pMEAN, float* pWf,
                      float* Hout, int round_out) {
    GemmSrcs pre; pre.s[0] = HinR; pre.s[1] = HinR; pre.s[2] = HinR; pre.s[3] = HinR;
    // A' (+bias) and B in one launch (blockIdx.x selects half)
    mma_gemm<<<dim3(2, (NNODES + 127) / 128), 256, SMEM_BYTES>>>(
        pre, wpreR, b_pre, pA, pB, NNODES, 128 / 32, 0, 0);
    fuse_kernel<<<513, 128>>>(w_post, b_post, w_lin, b_lin);
    aggregate_kernel<<<(NNODES + 7) / 8, 256>>>();
    GemmSrcs cat; cat.s[0] = HinR; cat.s[1] = pMEAN; cat.s[2] = pM; cat.s[3] = pS;
    mma_gemm<<<dim3(1, (NNODES + 127) / 128), 256, SMEM_BYTES>>>(
        cat, pWf, pWf + 512 * FDIM, Hout, Hout, NNODES, 512 / 32, 1, round_out);
}

extern "C" void kernel_launch(void* const* d_in, const int* in_sizes, int n_in,
                              void* d_out, int out_size) {
    const float* x      = (const float*)d_in[0];
    const int*   ei     = (const int*)  d_in[1];
    const float* w1_pre = (const float*)d_in[2];
    const float* b1_pre = (const float*)d_in[3];
    const float* w1_post= (const float*)d_in[4];
    const float* b1_post= (const float*)d_in[5];
    const float* w1_lin = (const float*)d_in[6];
    const float* b1_lin = (const float*)d_in[7];
    const float* w2_pre = (const float*)d_in[8];
    const float* b2_pre = (const float*)d_in[9];
    const float* w2_post= (const float*)d_in[10];
    const float* b2_post= (const float*)d_in[11];
    const float* w2_lin = (const float*)d_in[12];
    const float* b2_lin = (const float*)d_in[13];
    const float* w_out  = (const float*)d_in[14];
    const float* b_out  = (const float*)d_in[15];
    float* out = (float*)d_out;

    static int smem_set = 0;
    if (!smem_set) {
        cudaFuncSetAttribute(mma_gemm, cudaFuncAttributeMaxDynamicSharedMemorySize,
                             SMEM_BYTES);
        smem_set = 1;
    }

    void *pA, *pB, *pH, *pH2, *pS, *pM, *pMEAN, *pX, *pWf, *pWpreR, *pHist, *pCur;
    cudaGetSymbolAddress(&pA, g_A);
    cudaGetSymbolAddress(&pB, g_B);
    cudaGetSymbolAddress(&pH, g_H);
    cudaGetSymbolAddress(&pH2, g_H2);
    cudaGetSymbolAddress(&pS, g_S);
    cudaGetSymbolAddress(&pM, g_M);
    cudaGetSymbolAddress(&pMEAN, g_MEAN);
    cudaGetSymbolAddress(&pX, g_X);
    cudaGetSymbolAddress(&pWf, g_Wf);
    cudaGetSymbolAddress(&pWpreR, g_WpreR);
    cudaGetSymbolAddress(&pHist, g_hist);
    cudaGetSymbolAddress(&pCur, g_cur);

    const int* srcp = ei;           // edge_index[0]
    const int* dstp = ei + NEDGES;  // edge_index[1]

    // counting sort of edges by dst (shared by both layers)
    cudaMemsetAsync(pHist, 0, NNODES * sizeof(int));
    cudaMemsetAsync(pCur,  0, NNODES * sizeof(int));
    hist_kernel<<<(NEDGES + 255) / 256, 256>>>(dstp);
    scan_kernel<<<1, 1024>>>();
    scatter_kernel<<<(NEDGES + 255) / 256, 256>>>(srcp, dstp);

    // tf32-round GEMM inputs at the producers
    cvt_kernel<<<(NNODES * FDIM + 255) / 256, 256>>>(x, (float*)pX, NNODES * FDIM);
    cvt_kernel<<<(256 * FDIM + 255) / 256, 256>>>(w1_pre, (float*)pWpreR, 256 * FDIM);
    cvt_kernel<<<(256 * FDIM + 255) / 256, 256>>>(w2_pre, (float*)pWpreR + 256 * FDIM,
                                                  256 * FDIM);

    // layer 1: g_X -> g_H (rounded, feeds layer-2 tensor GEMMs)
    run_layer((const float*)pX, (const float*)pWpreR, b1_pre,
              w1_post, b1_post, w1_lin, b1_lin,
              (float*)pA, (float*)pB, (float*)pH,
              (float*)pS, (float*)pM, (float*)pMEAN, (float*)pWf,
              (float*)pH, 1);
    // layer 2: g_H -> g_H2 (unrounded, feeds fp32 output GEMM)
    run_layer((const float*)pH, (const float*)pWpreR + 256 * FDIM, b2_pre,
              w2_post, b2_post, w2_lin, b2_lin,
              (float*)pA, (float*)pB, (float*)pH,
              (float*)pS, (float*)pM, (float*)pMEAN, (float*)pWf,
              (float*)pH2, 0);
    // output: g_H2 @ w_out + b_out (fp32 SIMT; tiny)
    gemm_std<<<dim3(1, (NNODES + BM - 1) / BM), 256>>>(
        (const float*)pH2, w_out, b_out, out, NNODES, FDIM, CLS, 0);
}

// round 3
// speedup vs baseline: 2.2075x; 1.0579x over previous
#include <cuda_runtime.h>
#include <math.h>
#include <stdint.h>

#define NNODES 50000
#define NEDGES 500000
#define FDIM   128
#define CLS    40

// ---------------- scratch (static device globals; no allocation) ------------
__device__ float g_A   [NNODES * FDIM];   // A' = x @ W_top + b_pre (fp32)
__device__ float g_B   [NNODES * FDIM];   // B  = x @ W_bot        (fp32)
__device__ float g_S   [NNODES * FDIM];   // SUM aggregator  (fp32)
__device__ float g_M   [NNODES * FDIM];   // MAX aggregator  (fp32)
__device__ float g_MEAN[NNODES * FDIM];   // MEAN aggregator (fp32)
__device__ float g_H   [NNODES * FDIM];   // hidden after layer 1 (fp32)
__device__ float g_H2  [NNODES * FDIM];   // hidden after layer 2 (fp32)
__device__ float g_Wf  [513 * FDIM];      // fused W' (512 rows, tf32) + fused bias (fp32)
__device__ float g_WpreR[2 * 256 * FDIM]; // tf32-rounded w1_pre, w2_pre
__device__ int   g_hist[NNODES];
__device__ int   g_off [NNODES + 1];
__device__ int   g_cur [NNODES];
__device__ int   g_ssrc[NEDGES];          // src ids grouped (counting-sorted) by dst

// ---------------- helpers ---------------------------------------------------
__device__ __forceinline__ float tf32r(float x) {
    unsigned u;
    asm("cvt.rna.tf32.f32 %0, %1;" : "=r"(u) : "f"(x));
    return __uint_as_float(u);
}

__device__ __forceinline__ unsigned tf32u(float x) {
    unsigned u;
    asm("cvt.rna.tf32.f32 %0, %1;" : "=r"(u) : "f"(x));
    return u;
}

__device__ __forceinline__ void cpasync16(void* dst, const void* src, bool pred) {
    unsigned sa = (unsigned)__cvta_generic_to_shared(dst);
    int sz = pred ? 16 : 0;
    asm volatile("cp.async.cg.shared.global [%0], [%1], 16, %2;\n"
                 :: "r"(sa), "l"(src), "r"(sz));
}

__device__ __forceinline__ void mma_tf32(float* c, const unsigned* a,
                                         unsigned b0, unsigned b1) {
    asm volatile(
        "mma.sync.aligned.m16n8k8.row.col.f32.tf32.tf32.f32 "
        "{%0,%1,%2,%3}, {%4,%5,%6,%7}, {%8,%9}, {%0,%1,%2,%3};"
        : "+f"(c[0]), "+f"(c[1]), "+f"(c[2]), "+f"(c[3])
        : "r"(a[0]), "r"(a[1]), "r"(a[2]), "r"(a[3]), "r"(b0), "r"(b1));
}

// ---------------- graph preprocessing ---------------------------------------
__global__ void hist_kernel(const int* __restrict__ dst) {
    int i = blockIdx.x * blockDim.x + threadIdx.x;
    if (i < NEDGES) atomicAdd(&g_hist[dst[i]], 1);
}

__global__ void scan_kernel() {  // 1 block, 1024 threads
    __shared__ int s[1024];
    const int t = threadIdx.x;
    const int chunk = (NNODES + 1023) / 1024;
    int beg = t * chunk;
    int end = beg + chunk; if (end > NNODES) end = NNODES;
    int sum = 0;
    for (int i = beg; i < end; i++) sum += g_hist[i];
    s[t] = sum;
    __syncthreads();
    for (int d = 1; d < 1024; d <<= 1) {
        int v = (t >= d) ? s[t - d] : 0;
        __syncthreads();
        s[t] += v;
        __syncthreads();
    }
    int run = (t > 0) ? s[t - 1] : 0;
    for (int i = beg; i < end; i++) { g_off[i] = run; run += g_hist[i]; }
    if (t == 0) g_off[NNODES] = NEDGES;
}

__global__ void scatter_kernel(const int* __restrict__ src, const int* __restrict__ dst) {
    int i = blockIdx.x * blockDim.x + threadIdx.x;
    if (i >= NEDGES) return;
    int d = dst[i];
    int p = g_off[d] + atomicAdd(&g_cur[d], 1);
    g_ssrc[p] = src[i];
}

// tf32-round an array (weights only — activations are rounded in-register)
__global__ void cvt_kernel(const float* __restrict__ in, float* __restrict__ out, int n) {
    int i = blockIdx.x * blockDim.x + threadIdx.x;
    if (i < n) out[i] = tf32r(in[i]);
}

// ---------------- aggregation (warp/node) + finish, fused --------------------
// sum = cnt*A' + SB ; mean = sum/max(cnt,1) ; max = cnt>0 ? A' + MB : 0
__global__ void aggregate_kernel() {
    int node = (blockIdx.x * blockDim.x + threadIdx.x) >> 5;
    if (node >= NNODES) return;
    int lane = threadIdx.x & 31;
    int beg = g_off[node], end = g_off[node + 1];
    float s0 = 0.f, s1 = 0.f, s2 = 0.f, s3 = 0.f;
    float m0 = -3.4e38f, m1 = -3.4e38f, m2 = -3.4e38f, m3 = -3.4e38f;
    for (int e = beg; e < end; e++) {
        int sv = __ldg(&g_ssrc[e]);
        const float* rowp = g_B + (size_t)sv * FDIM;
        float v0 = __ldg(rowp + lane);
        float v1 = __ldg(rowp + lane + 32);
        float v2 = __ldg(rowp + lane + 64);
        float v3 = __ldg(rowp + lane + 96);
        s0 += v0; s1 += v1; s2 += v2; s3 += v3;
        m0 = fmaxf(m0, v0); m1 = fmaxf(m1, v1);
        m2 = fmaxf(m2, v2); m3 = fmaxf(m3, v3);
    }
    size_t o = (size_t)node * FDIM + lane;
    float c = (float)(end - beg);
    float ic = 1.f / fmaxf(c, 1.f);
    float a0 = g_A[o], a1 = g_A[o + 32], a2 = g_A[o + 64], a3 = g_A[o + 96];
    float t0 = fmaf(c, a0, s0), t1 = fmaf(c, a1, s1);
    float t2 = fmaf(c, a2, s2), t3 = fmaf(c, a3, s3);
    g_S[o]      = t0; g_S[o + 32] = t1; g_S[o + 64] = t2; g_S[o + 96] = t3;
    g_MEAN[o]      = t0 * ic; g_MEAN[o + 32] = t1 * ic;
    g_MEAN[o + 64] = t2 * ic; g_MEAN[o + 96] = t3 * ic;
    bool nz = (c > 0.f);
    g_M[o]      = nz ? (a0 + m0) : 0.f;
    g_M[o + 32] = nz ? (a1 + m1) : 0.f;
    g_M[o + 64] = nz ? (a2 + m2) : 0.f;
    g_M[o + 96] = nz ? (a3 + m3) : 0.f;
}

// ---------------- W' = [w_post; b_post] @ w_lin (+ b_lin on bias row) -------
__global__ void fuse_kernel(const float* __restrict__ wpost, const float* __restrict__ bpost,
                            const float* __restrict__ wlin,  const float* __restrict__ blin) {
    __shared__ float srow[FDIM];
    int r = blockIdx.x;    // 0..512
    int c = threadIdx.x;   // 0..127
    const float* row = (r < 512) ? (wpost + (size_t)r * FDIM) : bpost;
    srow[c] = row[c];
    __syncthreads();
    float acc = (r == 512) ? blin[c] : 0.f;
    #pragma unroll 8
    for (int k = 0; k < FDIM; k++) acc = fmaf(srow[k], wlin[k * FDIM + c], acc);
    g_Wf[r * FDIM + c] = (r < 512) ? tf32r(acc) : acc;  // bias row stays fp32
}

// ---------------- TF32 tensor-core GEMM -------------------------------------
// Block tile 128(M) x 128(N), K-slab 32, 2-stage cp.async pipeline.
// 8 warps 4(M) x 2(N); warp tile 32x64; mma m16n8k8.
// A fragments are tf32-rounded (rna) in-register at load — identical numerics
// to producer-side rounding, with no extra memory pass.
// If gridDim.x == 2: pre-GEMM mode — blockIdx.x selects weight half & output.
#define ASTRIDE 36
#define BSTRIDE 136
#define STAGEF  (128 * ASTRIDE + 32 * BSTRIDE)   // floats per stage = 8960
#define SMEM_BYTES (2 * STAGEF * 4)              // 71680

struct GemmSrcs { const float* s[4]; };

__global__ __launch_bounds__(256, 2)
void mma_gemm(GemmSrcs srcs, const float* __restrict__ W,
              const float* __restrict__ bias0,
              float* outA, float* outB,
              int M, int nIter, int relu) {
    extern __shared__ float smem[];
    const int tid = threadIdx.x;
    const int bm = blockIdx.y * 128;

    const float* Wb = W;
    float* out = outA;
    const float* bias = bias0;
    if (gridDim.x == 2 && blockIdx.x == 1) {
        Wb = W + 128 * 128;
        out = outB;
        bias = nullptr;
    }

    const int lane = tid & 31, wid = tid >> 5;
    const int wm = (wid >> 1) * 32, wn = (wid & 1) * 64;
    const int fr = lane >> 2, fc = lane & 3;

    float acc[2][8][4];
    #pragma unroll
    for (int mt = 0; mt < 2; mt++)
        #pragma unroll
        for (int nt = 0; nt < 8; nt++)
            #pragma unroll
            for (int j = 0; j < 4; j++) acc[mt][nt][j] = 0.f;

    auto loadStage = [&](int it, int stage) {
        int k0 = it * 32;
        const float* sp = srcs.s[(k0 >> 7) & 3];
        int kloc = k0 & 127;
        float* As = smem + stage * STAGEF;
        float* Bs = As + 128 * ASTRIDE;
        #pragma unroll
        for (int i = 0; i < 4; i++) {
            int id = tid + 256 * i;
            int arow = id >> 3, c4 = id & 7;
            bool p = (bm + arow) < M;
            cpasync16(As + arow * ASTRIDE + c4 * 4,
                      sp + (size_t)(bm + arow) * 128 + kloc + c4 * 4, p);
        }
        #pragma unroll
        for (int i = 0; i < 4; i++) {
            int id = tid + 256 * i;
            int krow = id >> 5, c4 = id & 31;
            cpasync16(Bs + krow * BSTRIDE + c4 * 4,
                      Wb + (size_t)(k0 + krow) * 128 + c4 * 4, true);
        }
        asm volatile("cp.async.commit_group;" ::: "memory");
    };

    loadStage(0, 0);
    for (int it = 0; it < nIter; ++it) {
        int cur = it & 1;
        if (it + 1 < nIter) {
            loadStage(it + 1, cur ^ 1);
            asm volatile("cp.async.wait_group 1;" ::: "memory");
        } else {
            asm volatile("cp.async.wait_group 0;" ::: "memory");
        }
        __syncthreads();

        const float* As = smem + cur * STAGEF;
        const float* Bs = As + 128 * ASTRIDE;
        #pragma unroll
        for (int kk = 0; kk < 32; kk += 8) {
            unsigned af[2][4];
            #pragma unroll
            for (int mt = 0; mt < 2; mt++) {
                int m0 = wm + mt * 16;
                af[mt][0] = tf32u(As[(m0 + fr)     * ASTRIDE + kk + fc]);
                af[mt][1] = tf32u(As[(m0 + fr + 8) * ASTRIDE + kk + fc]);
                af[mt][2] = tf32u(As[(m0 + fr)     * ASTRIDE + kk + fc + 4]);
                af[mt][3] = tf32u(As[(m0 + fr + 8) * ASTRIDE + kk + fc + 4]);
            }
            #pragma unroll
            for (int nt = 0; nt < 8; nt++) {
                int n0 = wn + nt * 8;
                unsigned b0 = __float_as_uint(Bs[(kk + fc)     * BSTRIDE + n0 + fr]);
                unsigned b1 = __float_as_uint(Bs[(kk + 4 + fc) * BSTRIDE + n0 + fr]);
                mma_tf32(acc[0][nt], af[0], b0, b1);
                mma_tf32(acc[1][nt], af[1], b0, b1);
            }
        }
        __syncthreads();
    }

    #pragma unroll
    for (int mt = 0; mt < 2; mt++) {
        #pragma unroll
        for (int nt = 0; nt < 8; nt++) {
            int r0 = bm + wm + mt * 16 + fr;
            int cc = wn + nt * 8 + 2 * fc;
            float b0 = 0.f, b1 = 0.f;
            if (bias) { b0 = bias[cc]; b1 = bias[cc + 1]; }
            float v0 = acc[mt][nt][0] + b0, v1 = acc[mt][nt][1] + b1;
            float v2 = acc[mt][nt][2] + b0, v3 = acc[mt][nt][3] + b1;
            if (relu) {
                v0 = fmaxf(v0, 0.f); v1 = fmaxf(v1, 0.f);
                v2 = fmaxf(v2, 0.f); v3 = fmaxf(v3, 0.f);
            }
            if (r0 < M) {
                float2 o = make_float2(v0, v1);
                *(float2*)(out + (size_t)r0 * 128 + cc) = o;
            }
            if (r0 + 8 < M) {
                float2 o = make_float2(v2, v3);
                *(float2*)(out + (size_t)(r0 + 8) * 128 + cc) = o;
            }
        }
    }
}

// ---------------- fp32 SIMT GEMM for the small output projection ------------
#define BM 128
#define BN 64
#define BK 16

__global__ __launch_bounds__(256)
void gemm_std(const float* __restrict__ A, const float* __restrict__ W,
              const float* __restrict__ bias, float* __restrict__ C,
              int M, int K, int Nout, int relu) {
    __shared__ float As[BK][BM + 4];
    __shared__ float Ws[BK][BN];
    const int tid = threadIdx.x;
    const int tx = tid & 15;
    const int ty = tid >> 4;
    const int rowBase = blockIdx.y * BM;
    const int colBase = blockIdx.x * BN;
    float acc[8][4] = {};

    for (int k0 = 0; k0 < K; k0 += BK) {
        #pragma unroll
        for (int r = 0; r < 2; r++) {
            int id = tid + 256 * r;
            int arow = id >> 2;
            int k4 = (id & 3) * 4;
            int grow = rowBase + arow;
            float4 v = make_float4(0.f, 0.f, 0.f, 0.f);
            if (grow < M) v = *(const float4*)(A + (size_t)grow * K + k0 + k4);
            As[k4 + 0][arow] = v.x; As[k4 + 1][arow] = v.y;
            As[k4 + 2][arow] = v.z; As[k4 + 3][arow] = v.w;
        }
        {
            int wk = tid >> 4;
            int wc = (tid & 15) * 4;
            int gc = colBase + wc;
            float4 v = make_float4(0.f, 0.f, 0.f, 0.f);
            if (gc < Nout) v = *(const float4*)(W + (size_t)(k0 + wk) * Nout + gc);
            *(float4*)&Ws[wk][wc] = v;
        }
        __syncthreads();
        #pragma unroll
        for (int kk = 0; kk < BK; kk++) {
            float4 a0 = *(const float4*)&As[kk][ty * 8];
            float4 a1 = *(const float4*)&As[kk][ty * 8 + 4];
            float4 bv = *(const float4*)&Ws[kk][tx * 4];
            float a[8] = {a0.x, a0.y, a0.z, a0.w, a1.x, a1.y, a1.z, a1.w};
            float b[4] = {bv.x, bv.y, bv.z, bv.w};
            #pragma unroll
            for (int i = 0; i < 8; i++)
                #pragma unroll
                for (int j = 0; j < 4; j++)
                    acc[i][j] = fmaf(a[i], b[j], acc[i][j]);
        }
        __syncthreads();
    }

    int gc = colBase + tx * 4;
    if (gc >= Nout) return;
    float4 bb = make_float4(0.f, 0.f, 0.f, 0.f);
    if (bias) bb = *(const float4*)(bias + gc);
    #pragma unroll
    for (int i = 0; i < 8; i++) {
        int grow = rowBase + ty * 8 + i;
        if (grow >= M) continue;
        float4 o;
        o.x = acc[i][0] + bb.x; o.y = acc[i][1] + bb.y;
        o.z = acc[i][2] + bb.z; o.w = acc[i][3] + bb.w;
        if (relu) {
            o.x = fmaxf(o.x, 0.f); o.y = fmaxf(o.y, 0.f);
            o.z = fmaxf(o.z, 0.f); o.w = fmaxf(o.w, 0.f);
        }
        *(float4*)(C + (size_t)grow * Nout + gc) = o;
    }
}

// ---------------- host side -------------------------------------------------
static void run_layer(const float* Hin,           // raw fp32 activations
                      const float* wpreR,         // tf32-rounded w_pre [256x128]
                      const float* b_pre,
                      const float* w_post, const float* b_post,
                      const float* w_lin, const float* b_lin,
                      float* pA, float* pB,
                      float* pS, float* pM, float* pMEAN, float* pWf,
                      float* Hout) {
    GemmSrcs pre; pre.s[0] = Hin; pre.s[1] = Hin; pre.s[2] = Hin; pre.s[3] = Hin;
    mma_gemm<<<dim3(2, (NNODES + 127) / 128), 256, SMEM_BYTES>>>(
        pre, wpreR, b_pre, pA, pB, NNODES, 128 / 32, 0);
    fuse_kernel<<<513, 128>>>(w_post, b_post, w_lin, b_lin);
    aggregate_kernel<<<(NNODES + 7) / 8, 256>>>();
    GemmSrcs cat; cat.s[0] = Hin; cat.s[1] = pMEAN; cat.s[2] = pM; cat.s[3] = pS;
    mma_gemm<<<dim3(1, (NNODES + 127) / 128), 256, SMEM_BYTES>>>(
        cat, pWf, pWf + 512 * FDIM, Hout, Hout, NNODES, 512 / 32, 1);
}

extern "C" void kernel_launch(void* const* d_in, const int* in_sizes, int n_in,
                              void* d_out, int out_size) {
    const float* x      = (const float*)d_in[0];
    const int*   ei     = (const int*)  d_in[1];
    const float* w1_pre = (const float*)d_in[2];
    const float* b1_pre = (const float*)d_in[3];
    const float* w1_post= (const float*)d_in[4];
    const float* b1_post= (const float*)d_in[5];
    const float* w1_lin = (const float*)d_in[6];
    const float* b1_lin = (const float*)d_in[7];
    const float* w2_pre = (const float*)d_in[8];
    const float* b2_pre = (const float*)d_in[9];
    const float* w2_post= (const float*)d_in[10];
    const float* b2_post= (const float*)d_in[11];
    const float* w2_lin = (const float*)d_in[12];
    const float* b2_lin = (const float*)d_in[13];
    const float* w_out  = (const float*)d_in[14];
    const float* b_out  = (const float*)d_in[15];
    float* out = (float*)d_out;

    static int smem_set = 0;
    if (!smem_set) {
        cudaFuncSetAttribute(mma_gemm, cudaFuncAttributeMaxDynamicSharedMemorySize,
                             SMEM_BYTES);
        smem_set = 1;
    }

    void *pA, *pB, *pH, *pH2, *pS, *pM, *pMEAN, *pWf, *pWpreR, *pHist, *pCur;
    cudaGetSymbolAddress(&pA, g_A);
    cudaGetSymbolAddress(&pB, g_B);
    cudaGetSymbolAddress(&pH, g_H);
    cudaGetSymbolAddress(&pH2, g_H2);
    cudaGetSymbolAddress(&pS, g_S);
    cudaGetSymbolAddress(&pM, g_M);
    cudaGetSymbolAddress(&pMEAN, g_MEAN);
    cudaGetSymbolAddress(&pWf, g_Wf);
    cudaGetSymbolAddress(&pWpreR, g_WpreR);
    cudaGetSymbolAddress(&pHist, g_hist);
    cudaGetSymbolAddress(&pCur, g_cur);

    const int* srcp = ei;           // edge_index[0]
    const int* dstp = ei + NEDGES;  // edge_index[1]

    // counting sort of edges by dst (shared by both layers)
    cudaMemsetAsync(pHist, 0, NNODES * sizeof(int));
    cudaMemsetAsync(pCur,  0, NNODES * sizeof(int));
    hist_kernel<<<(NEDGES + 255) / 256, 256>>>(dstp);
    scan_kernel<<<1, 1024>>>();
    scatter_kernel<<<(NEDGES + 255) / 256, 256>>>(srcp, dstp);

    // tf32-round pre-weights only (tiny)
    cvt_kernel<<<(256 * FDIM + 255) / 256, 256>>>(w1_pre, (float*)pWpreR, 256 * FDIM);
    cvt_kernel<<<(256 * FDIM + 255) / 256, 256>>>(w2_pre, (float*)pWpreR + 256 * FDIM,
                                                  256 * FDIM);

    // layer 1: x -> g_H
    run_layer(x, (const float*)pWpreR, b1_pre,
              w1_post, b1_post, w1_lin, b1_lin,
              (float*)pA, (float*)pB,
              (float*)pS, (float*)pM, (float*)pMEAN, (float*)pWf,
              (float*)pH);
    // layer 2: g_H -> g_H2
    run_layer((const float*)pH, (const float*)pWpreR + 256 * FDIM, b2_pre,
              w2_post, b2_post, w2_lin, b2_lin,
              (float*)pA, (float*)pB,
              (float*)pS, (float*)pM, (float*)pMEAN, (float*)pWf,
              (float*)pH2);
    // output: g_H2 @ w_out + b_out (fp32 SIMT; protects rel_err margin)
    gemm_std<<<dim3(1, (NNODES + BM - 1) / BM), 256>>>(
        (const float*)pH2, w_out, b_out, out, NNODES, FDIM, CLS, 0);
}

// round 4
// speedup vs baseline: 2.3653x; 1.0715x over previous
#include <cuda_runtime.h>
#include <math.h>
#include <stdint.h>

#define NNODES 50000
#define NEDGES 500000
#define FDIM   128
#define CLS    40

// ---------------- scratch (static device globals; no allocation) ------------
__device__ float g_A   [NNODES * FDIM];   // A' = x @ W_top + b_pre (fp32)
__device__ float g_B   [NNODES * FDIM];   // B  = x @ W_bot        (fp32)
__device__ float g_S   [NNODES * FDIM];   // SUM aggregator  (fp32)
__device__ float g_M   [NNODES * FDIM];   // MAX aggregator  (fp32)
__device__ float g_MEAN[NNODES * FDIM];   // MEAN aggregator (fp32)
__device__ float g_H   [NNODES * FDIM];   // hidden after layer 1 (fp32)
__device__ float g_H2  [NNODES * FDIM];   // hidden after layer 2 (fp32)
__device__ float g_Wf  [513 * FDIM];      // fused W' (512 rows, tf32) + fused bias (fp32)
__device__ float g_WpreR[2 * 256 * FDIM]; // tf32-rounded w1_pre, w2_pre
__device__ float g_WoR [FDIM * CLS];      // tf32-rounded w_out
__device__ int   g_hist[NNODES];
__device__ int   g_off [NNODES + 1];
__device__ int   g_cur [NNODES];
__device__ int   g_ssrc[NEDGES];          // src ids grouped (counting-sorted) by dst

// ---------------- helpers ---------------------------------------------------
__device__ __forceinline__ float tf32r(float x) {
    unsigned u;
    asm("cvt.rna.tf32.f32 %0, %1;" : "=r"(u) : "f"(x));
    return __uint_as_float(u);
}

__device__ __forceinline__ unsigned tf32u(float x) {
    unsigned u;
    asm("cvt.rna.tf32.f32 %0, %1;" : "=r"(u) : "f"(x));
    return u;
}

__device__ __forceinline__ void cpasync16(void* dst, const void* src, bool pred) {
    unsigned sa = (unsigned)__cvta_generic_to_shared(dst);
    int sz = pred ? 16 : 0;
    asm volatile("cp.async.cg.shared.global [%0], [%1], 16, %2;\n"
                 :: "r"(sa), "l"(src), "r"(sz));
}

__device__ __forceinline__ void mma_tf32(float* c, const unsigned* a,
                                         unsigned b0, unsigned b1) {
    asm volatile(
        "mma.sync.aligned.m16n8k8.row.col.f32.tf32.tf32.f32 "
        "{%0,%1,%2,%3}, {%4,%5,%6,%7}, {%8,%9}, {%0,%1,%2,%3};"
        : "+f"(c[0]), "+f"(c[1]), "+f"(c[2]), "+f"(c[3])
        : "r"(a[0]), "r"(a[1]), "r"(a[2]), "r"(a[3]), "r"(b0), "r"(b1));
}

// ---------------- graph preprocessing ---------------------------------------
__global__ void hist_kernel(const int* __restrict__ dst) {
    int i = blockIdx.x * blockDim.x + threadIdx.x;
    if (i < NEDGES) atomicAdd(&g_hist[dst[i]], 1);
}

__global__ void scan_kernel() {  // 1 block, 1024 threads
    __shared__ int s[1024];
    const int t = threadIdx.x;
    const int chunk = (NNODES + 1023) / 1024;
    int beg = t * chunk;
    int end = beg + chunk; if (end > NNODES) end = NNODES;
    int sum = 0;
    for (int i = beg; i < end; i++) sum += g_hist[i];
    s[t] = sum;
    __syncthreads();
    for (int d = 1; d < 1024; d <<= 1) {
        int v = (t >= d) ? s[t - d] : 0;
        __syncthreads();
        s[t] += v;
        __syncthreads();
    }
    int run = (t > 0) ? s[t - 1] : 0;
    for (int i = beg; i < end; i++) { g_off[i] = run; run += g_hist[i]; }
    if (t == 0) g_off[NNODES] = NEDGES;
}

__global__ void scatter_kernel(const int* __restrict__ src, const int* __restrict__ dst) {
    int i = blockIdx.x * blockDim.x + threadIdx.x;
    if (i >= NEDGES) return;
    int d = dst[i];
    int p = g_off[d] + atomicAdd(&g_cur[d], 1);
    g_ssrc[p] = src[i];
}

// tf32-round an array (weights only — activations are rounded in-register)
__global__ void cvt_kernel(const float* __restrict__ in, float* __restrict__ out, int n) {
    int i = blockIdx.x * blockDim.x + threadIdx.x;
    if (i < n) out[i] = tf32r(in[i]);
}

// ---------------- aggregation (warp/node, float4 lanes) ----------------------
// sum = cnt*A' + SB ; mean = sum/max(cnt,1) ; max = cnt>0 ? A' + MB : 0
__global__ void aggregate_kernel() {
    int node = (blockIdx.x * blockDim.x + threadIdx.x) >> 5;
    if (node >= NNODES) return;
    int lane = threadIdx.x & 31;
    int beg = g_off[node], end = g_off[node + 1];
    const float4* Bv = (const float4*)g_B;          // 32 float4 per row
    float4 s = make_float4(0.f, 0.f, 0.f, 0.f);
    float4 m = make_float4(-3.4e38f, -3.4e38f, -3.4e38f, -3.4e38f);
    int e = beg;
    for (; e + 1 < end; e += 2) {
        int sv0 = __ldg(&g_ssrc[e]);
        int sv1 = __ldg(&g_ssrc[e + 1]);
        float4 v0 = __ldg(&Bv[(size_t)sv0 * 32 + lane]);
        float4 v1 = __ldg(&Bv[(size_t)sv1 * 32 + lane]);
        s.x += v0.x + v1.x; s.y += v0.y + v1.y;
        s.z += v0.z + v1.z; s.w += v0.w + v1.w;
        m.x = fmaxf(m.x, fmaxf(v0.x, v1.x)); m.y = fmaxf(m.y, fmaxf(v0.y, v1.y));
        m.z = fmaxf(m.z, fmaxf(v0.z, v1.z)); m.w = fmaxf(m.w, fmaxf(v0.w, v1.w));
    }
    if (e < end) {
        int sv = __ldg(&g_ssrc[e]);
        float4 v = __ldg(&Bv[(size_t)sv * 32 + lane]);
        s.x += v.x; s.y += v.y; s.z += v.z; s.w += v.w;
        m.x = fmaxf(m.x, v.x); m.y = fmaxf(m.y, v.y);
        m.z = fmaxf(m.z, v.z); m.w = fmaxf(m.w, v.w);
    }
    size_t o = (size_t)node * 32 + lane;
    float c = (float)(end - beg);
    float ic = 1.f / fmaxf(c, 1.f);
    float4 a = ((const float4*)g_A)[o];
    float4 t;
    t.x = fmaf(c, a.x, s.x); t.y = fmaf(c, a.y, s.y);
    t.z = fmaf(c, a.z, s.z); t.w = fmaf(c, a.w, s.w);
    ((float4*)g_S)[o] = t;
    float4 mn = make_float4(t.x * ic, t.y * ic, t.z * ic, t.w * ic);
    ((float4*)g_MEAN)[o] = mn;
    bool nz = (c > 0.f);
    float4 mx;
    mx.x = nz ? (a.x + m.x) : 0.f; mx.y = nz ? (a.y + m.y) : 0.f;
    mx.z = nz ? (a.z + m.z) : 0.f; mx.w = nz ? (a.w + m.w) : 0.f;
    ((float4*)g_M)[o] = mx;
}

// ---------------- W' = [w_post; b_post] @ w_lin (+ b_lin on bias row) -------
__global__ void fuse_kernel(const float* __restrict__ wpost, const float* __restrict__ bpost,
                            const float* __restrict__ wlin,  const float* __restrict__ blin) {
    __shared__ float srow[FDIM];
    int r = blockIdx.x;    // 0..512
    int c = threadIdx.x;   // 0..127
    const float* row = (r < 512) ? (wpost + (size_t)r * FDIM) : bpost;
    srow[c] = row[c];
    __syncthreads();
    float acc = (r == 512) ? blin[c] : 0.f;
    #pragma unroll 8
    for (int k = 0; k < FDIM; k++) acc = fmaf(srow[k], wlin[k * FDIM + c], acc);
    g_Wf[r * FDIM + c] = (r < 512) ? tf32r(acc) : acc;  // bias row stays fp32
}

// ---------------- TF32 tensor-core GEMM (main) -------------------------------
#define ASTRIDE 36
#define BSTRIDE 136
#define STAGEF  (128 * ASTRIDE + 32 * BSTRIDE)
#define SMEM_BYTES (2 * STAGEF * 4)

struct GemmSrcs { const float* s[4]; };

__global__ __launch_bounds__(256, 2)
void mma_gemm(GemmSrcs srcs, const float* __restrict__ W,
              const float* __restrict__ bias0,
              float* outA, float* outB,
              int M, int nIter, int relu) {
    extern __shared__ float smem[];
    const int tid = threadIdx.x;
    const int bm = blockIdx.y * 128;

    const float* Wb = W;
    float* out = outA;
    const float* bias = bias0;
    if (gridDim.x == 2 && blockIdx.x == 1) {
        Wb = W + 128 * 128;
        out = outB;
        bias = nullptr;
    }

    const int lane = tid & 31, wid = tid >> 5;
    const int wm = (wid >> 1) * 32, wn = (wid & 1) * 64;
    const int fr = lane >> 2, fc = lane & 3;

    float acc[2][8][4];
    #pragma unroll
    for (int mt = 0; mt < 2; mt++)
        #pragma unroll
        for (int nt = 0; nt < 8; nt++)
            #pragma unroll
            for (int j = 0; j < 4; j++) acc[mt][nt][j] = 0.f;

    auto loadStage = [&](int it, int stage) {
        int k0 = it * 32;
        const float* sp = srcs.s[(k0 >> 7) & 3];
        int kloc = k0 & 127;
        float* As = smem + stage * STAGEF;
        float* Bs = As + 128 * ASTRIDE;
        #pragma unroll
        for (int i = 0; i < 4; i++) {
            int id = tid + 256 * i;
            int arow = id >> 3, c4 = id & 7;
            bool p = (bm + arow) < M;
            cpasync16(As + arow * ASTRIDE + c4 * 4,
                      sp + (size_t)(bm + arow) * 128 + kloc + c4 * 4, p);
        }
        #pragma unroll
        for (int i = 0; i < 4; i++) {
            int id = tid + 256 * i;
            int krow = id >> 5, c4 = id & 31;
            cpasync16(Bs + krow * BSTRIDE + c4 * 4,
                      Wb + (size_t)(k0 + krow) * 128 + c4 * 4, true);
        }
        asm volatile("cp.async.commit_group;" ::: "memory");
    };

    loadStage(0, 0);
    for (int it = 0; it < nIter; ++it) {
        int cur = it & 1;
        if (it + 1 < nIter) {
            loadStage(it + 1, cur ^ 1);
            asm volatile("cp.async.wait_group 1;" ::: "memory");
        } else {
            asm volatile("cp.async.wait_group 0;" ::: "memory");
        }
        __syncthreads();

        const float* As = smem + cur * STAGEF;
        const float* Bs = As + 128 * ASTRIDE;
        #pragma unroll
        for (int kk = 0; kk < 32; kk += 8) {
            unsigned af[2][4];
            #pragma unroll
            for (int mt = 0; mt < 2; mt++) {
                int m0 = wm + mt * 16;
                af[mt][0] = tf32u(As[(m0 + fr)     * ASTRIDE + kk + fc]);
                af[mt][1] = tf32u(As[(m0 + fr + 8) * ASTRIDE + kk + fc]);
                af[mt][2] = tf32u(As[(m0 + fr)     * ASTRIDE + kk + fc + 4]);
                af[mt][3] = tf32u(As[(m0 + fr + 8) * ASTRIDE + kk + fc + 4]);
            }
            #pragma unroll
            for (int nt = 0; nt < 8; nt++) {
                int n0 = wn + nt * 8;
                unsigned b0 = __float_as_uint(Bs[(kk + fc)     * BSTRIDE + n0 + fr]);
                unsigned b1 = __float_as_uint(Bs[(kk + 4 + fc) * BSTRIDE + n0 + fr]);
                mma_tf32(acc[0][nt], af[0], b0, b1);
                mma_tf32(acc[1][nt], af[1], b0, b1);
            }
        }
        __syncthreads();
    }

    #pragma unroll
    for (int mt = 0; mt < 2; mt++) {
        #pragma unroll
        for (int nt = 0; nt < 8; nt++) {
            int r0 = bm + wm + mt * 16 + fr;
            int cc = wn + nt * 8 + 2 * fc;
            float b0 = 0.f, b1 = 0.f;
            if (bias) { b0 = bias[cc]; b1 = bias[cc + 1]; }
            float v0 = acc[mt][nt][0] + b0, v1 = acc[mt][nt][1] + b1;
            float v2 = acc[mt][nt][2] + b0, v3 = acc[mt][nt][3] + b1;
            if (relu) {
                v0 = fmaxf(v0, 0.f); v1 = fmaxf(v1, 0.f);
                v2 = fmaxf(v2, 0.f); v3 = fmaxf(v3, 0.f);
            }
            if (r0 < M) {
                float2 o = make_float2(v0, v1);
                *(float2*)(out + (size_t)r0 * 128 + cc) = o;
            }
            if (r0 + 8 < M) {
                float2 o = make_float2(v2, v3);
                *(float2*)(out + (size_t)(r0 + 8) * 128 + cc) = o;
            }
        }
    }
}

// ---------------- TF32 MMA output projection: out = H2 @ Wo + b -------------
// Block: 128 rows, full N=40, K=128 one-shot smem load. 8 warps × 16 rows.
#define OAST 132            // A smem row stride
#define OBST 44             // W smem row stride
#define OSMEM_F (128 * OAST + 128 * OBST)
#define OSMEM_BYTES (OSMEM_F * 4)

__global__ __launch_bounds__(256, 2)
void out_gemm(const float* __restrict__ H2, const float* __restrict__ Wo,
              const float* __restrict__ bias, float* __restrict__ out, int M) {
    extern __shared__ float smem[];
    float* As = smem;
    float* Bs = smem + 128 * OAST;
    const int tid = threadIdx.x;
    const int bm = blockIdx.x * 128;
    const int lane = tid & 31, wid = tid >> 5;
    const int fr = lane >> 2, fc = lane & 3;

    // load A tile: 128 rows x 128 cols
    #pragma unroll
    for (int i = 0; i < 16; i++) {
        int id = tid + 256 * i;
        int arow = id >> 5, c4 = id & 31;
        bool p = (bm + arow) < M;
        cpasync16(As + arow * OAST + c4 * 4,
                  H2 + (size_t)(bm + arow) * 128 + c4 * 4, p);
    }
    // load W: 128 rows x 40 cols (10 float4 per row)
    #pragma unroll
    for (int i = 0; i < 5; i++) {
        int id = tid + 256 * i;
        int wrow = id / 10, c4 = id % 10;
        cpasync16(Bs + wrow * OBST + c4 * 4,
                  Wo + (size_t)wrow * CLS + c4 * 4, true);
    }
    asm volatile("cp.async.commit_group;" ::: "memory");
    asm volatile("cp.async.wait_group 0;" ::: "memory");
    __syncthreads();

    const int m0 = wid * 16;
    float acc[5][4];
    #pragma unroll
    for (int nt = 0; nt < 5; nt++)
        #pragma unroll
        for (int j = 0; j < 4; j++) acc[nt][j] = 0.f;

    #pragma unroll
    for (int kk = 0; kk < 128; kk += 8) {
        unsigned af[4];
        af[0] = tf32u(As[(m0 + fr)     * OAST + kk + fc]);
        af[1] = tf32u(As[(m0 + fr + 8) * OAST + kk + fc]);
        af[2] = tf32u(As[(m0 + fr)     * OAST + kk + fc + 4]);
        af[3] = tf32u(As[(m0 + fr + 8) * OAST + kk + fc + 4]);
        #pragma unroll
        for (int nt = 0; nt < 5; nt++) {
            int n0 = nt * 8;
            unsigned b0 = __float_as_uint(Bs[(kk + fc)     * OBST + n0 + fr]);
            unsigned b1 = __float_as_uint(Bs[(kk + 4 + fc) * OBST + n0 + fr]);
            mma_tf32(acc[nt], af, b0, b1);
        }
    }

    #pragma unroll
    for (int nt = 0; nt < 5; nt++) {
        int r0 = bm + m0 + fr;
        int cc = nt * 8 + 2 * fc;
        float b0 = bias[cc], b1 = bias[cc + 1];
        if (r0 < M) {
            float2 o = make_float2(acc[nt][0] + b0, acc[nt][1] + b1);
            *(float2*)(out + (size_t)r0 * CLS + cc) = o;
        }
        if (r0 + 8 < M) {
            float2 o = make_float2(acc[nt][2] + b0, acc[nt][3] + b1);
            *(float2*)(out + (size_t)(r0 + 8) * CLS + cc) = o;
        }
    }
}

// ---------------- host side -------------------------------------------------
static void run_layer(const float* Hin,
                      const float* wpreR, const float* b_pre,
                      const float* w_post, const float* b_post,
                      const float* w_lin, const float* b_lin,
                      float* pA, float* pB,
                      float* pS, float* pM, float* pMEAN, float* pWf,
                      float* Hout) {
    GemmSrcs pre; pre.s[0] = Hin; pre.s[1] = Hin; pre.s[2] = Hin; pre.s[3] = Hin;
    mma_gemm<<<dim3(2, (NNODES + 127) / 128), 256, SMEM_BYTES>>>(
        pre, wpreR, b_pre, pA, pB, NNODES, 128 / 32, 0);
    fuse_kernel<<<513, 128>>>(w_post, b_post, w_lin, b_lin);
    aggregate_kernel<<<(NNODES + 7) / 8, 256>>>();
    GemmSrcs cat; cat.s[0] = Hin; cat.s[1] = pMEAN; cat.s[2] = pM; cat.s[3] = pS;
    mma_gemm<<<dim3(1, (NNODES + 127) / 128), 256, SMEM_BYTES>>>(
        cat, pWf, pWf + 512 * FDIM, Hout, Hout, NNODES, 512 / 32, 1);
}

extern "C" void kernel_launch(void* const* d_in, const int* in_sizes, int n_in,
                              void* d_out, int out_size) {
    const float* x      = (const float*)d_in[0];
    const int*   ei     = (const int*)  d_in[1];
    const float* w1_pre = (const float*)d_in[2];
    const float* b1_pre = (const float*)d_in[3];
    const float* w1_post= (const float*)d_in[4];
    const float* b1_post= (const float*)d_in[5];
    const float* w1_lin = (const float*)d_in[6];
    const float* b1_lin = (const float*)d_in[7];
    const float* w2_pre = (const float*)d_in[8];
    const float* b2_pre = (const float*)d_in[9];
    const float* w2_post= (const float*)d_in[10];
    const float* b2_post= (const float*)d_in[11];
    const float* w2_lin = (const float*)d_in[12];
    const float* b2_lin = (const float*)d_in[13];
    const float* w_out  = (const float*)d_in[14];
    const float* b_out  = (const float*)d_in[15];
    float* out = (float*)d_out;

    static int smem_set = 0;
    if (!smem_set) {
        cudaFuncSetAttribute(mma_gemm, cudaFuncAttributeMaxDynamicSharedMemorySize,
                             SMEM_BYTES);
        cudaFuncSetAttribute(out_gemm, cudaFuncAttributeMaxDynamicSharedMemorySize,
                             OSMEM_BYTES);
        smem_set = 1;
    }

    void *pA, *pB, *pH, *pH2, *pS, *pM, *pMEAN, *pWf, *pWpreR, *pWoR, *pHist, *pCur;
    cudaGetSymbolAddress(&pA, g_A);
    cudaGetSymbolAddress(&pB, g_B);
    cudaGetSymbolAddress(&pH, g_H);
    cudaGetSymbolAddress(&pH2, g_H2);
    cudaGetSymbolAddress(&pS, g_S);
    cudaGetSymbolAddress(&pM, g_M);
    cudaGetSymbolAddress(&pMEAN, g_MEAN);
    cudaGetSymbolAddress(&pWf, g_Wf);
    cudaGetSymbolAddress(&pWpreR, g_WpreR);
    cudaGetSymbolAddress(&pWoR, g_WoR);
    cudaGetSymbolAddress(&pHist, g_hist);
    cudaGetSymbolAddress(&pCur, g_cur);

    const int* srcp = ei;           // edge_index[0]
    const int* dstp = ei + NEDGES;  // edge_index[1]

    // counting sort of edges by dst (shared by both layers)
    cudaMemsetAsync(pHist, 0, NNODES * sizeof(int));
    cudaMemsetAsync(pCur,  0, NNODES * sizeof(int));
    hist_kernel<<<(NEDGES + 255) / 256, 256>>>(dstp);
    scan_kernel<<<1, 1024>>>();
    scatter_kernel<<<(NEDGES + 255) / 256, 256>>>(srcp, dstp);

    // tf32-round weights (tiny)
    cvt_kernel<<<(256 * FDIM + 255) / 256, 256>>>(w1_pre, (float*)pWpreR, 256 * FDIM);
    cvt_kernel<<<(256 * FDIM + 255) / 256, 256>>>(w2_pre, (float*)pWpreR + 256 * FDIM,
                                                  256 * FDIM);
    cvt_kernel<<<(FDIM * CLS + 255) / 256, 256>>>(w_out, (float*)pWoR, FDIM * CLS);

    // layer 1: x -> g_H
    run_layer(x, (const float*)pWpreR, b1_pre,
              w1_post, b1_post, w1_lin, b1_lin,
              (float*)pA, (float*)pB,
              (float*)pS, (float*)pM, (float*)pMEAN, (float*)pWf,
              (float*)pH);
    // layer 2: g_H -> g_H2
    run_layer((const float*)pH, (const float*)pWpreR + 256 * FDIM, b2_pre,
              w2_post, b2_post, w2_lin, b2_lin,
              (float*)pA, (float*)pB,
              (float*)pS, (float*)pM, (float*)pMEAN, (float*)pWf,
              (float*)pH2);
    // output projection (TF32 MMA)
    out_gemm<<<(NNODES + 127) / 128, 256, OSMEM_BYTES>>>(
        (const float*)pH2, (const float*)pWoR, b_out, out, NNODES);
}